// round 15
// baseline (speedup 1.0000x reference)
#include <cuda_runtime.h>

typedef unsigned long long u64;

#define TBLK  128
#define XSTR  129   // padded stride for transposed x tile (128 rows)

// g_ws layout (prep output)
#define OFF_S0 0        // 136*16 symmetric w0  (scaled a2)
#define OFF_S2 2176     // 136*16 symmetric w2  (scaled a2/sqrt3)
#define OFF_S4 4352     // 136*16 symmetric w4  (scaled a1; m-scales in epilogue)
#define OFF_A3 6528     // 120*16 antisym  w3   (scaled a1/sqrt2)
#define OFF_W1 8448     // 256*16 w1            (scaled a1)
#define W_TOTAL 12544

#define XTILE_FLOATS (64 * XSTR)                    // 8256
#define SMEM_A_BYTES ((8704 + XTILE_FLOATS) * 4)    // s4 + x tile
#define SMEM_B_BYTES ((6272 + XTILE_FLOATS) * 4)    // s0+s2+a3 + x tile
#define SMEM_C_BYTES ((4096 + XTILE_FLOATS) * 4)    // w1 + x tile

#define A1F    0.0625f
#define A2F    0.04419417382415922f
#define A2_3F  0.02551551815399144f
#define A1S2F  0.04419417382415922f
#define S2F    0.7071067811865476f
#define IS6F   0.4082482904638630f

__device__ float g_ws[W_TOTAL];

__global__ void prep_kernel(const float* __restrict__ w0, const float* __restrict__ w1,
                            const float* __restrict__ w2, const float* __restrict__ w3,
                            const float* __restrict__ w4)
{
    int idx = blockIdx.x * blockDim.x + threadIdx.x;
    if (idx >= 4096) return;
    int w = idx & 15;
    int v = (idx >> 4) & 15;
    int u = idx >> 8;
    int sidx = ((v * 16 + u) << 4) + w;

    g_ws[OFF_W1 + idx] = A1F * w1[idx];

    if (u <= v) {
        int p = u * 16 - (u * (u - 1)) / 2 + (v - u);
        float f0 = (u == v) ? w0[idx] : (w0[idx] + w0[sidx]);
        float f2 = (u == v) ? w2[idx] : (w2[idx] + w2[sidx]);
        float f4 = (u == v) ? w4[idx] : (w4[idx] + w4[sidx]);
        g_ws[OFF_S0 + p * 16 + w] = A2F   * f0;
        g_ws[OFF_S2 + p * 16 + w] = A2_3F * f2;
        g_ws[OFF_S4 + p * 16 + w] = A1F   * f4;
    }
    if (u < v) {
        int pa = 15 * u - (u * (u - 1)) / 2 + (v - u - 1);
        g_ws[OFF_A3 + pa * 16 + w] = A1S2F * (w3[idx] - w3[sidx]);
    }
}

// ---- packed fp32 helpers -------------------------------------------------
__device__ __forceinline__ u64 dup2(float s)
{
    unsigned int b = __float_as_uint(s);
    u64 r;
    asm("mov.b64 %0, {%1, %1};" : "=l"(r) : "r"(b));
    return r;
}
__device__ __forceinline__ void fma2(u64& d, u64 a, u64 b)
{
    asm("fma.rn.f32x2 %0, %1, %2, %0;" : "+l"(d) : "l"(a), "l"(b));
}
__device__ __forceinline__ u64 mul2(u64 a, u64 b)
{
    u64 d;
    asm("mul.rn.f32x2 %0, %1, %2;" : "=l"(d) : "l"(a), "l"(b));
    return d;
}
__device__ __forceinline__ void unpk(u64 v, float& lo, float& hi)
{
    unsigned int l, h;
    asm("mov.b64 {%0, %1}, %2;" : "=r"(l), "=r"(h) : "l"(v));
    lo = __uint_as_float(l);
    hi = __uint_as_float(h);
}

// ---- single-row axpy over one 16-float weight row ------------------------
__device__ __forceinline__ void axpy16(u64* a, const float* wb, u64 f)
{
    const ulonglong2* wr = reinterpret_cast<const ulonglong2*>(wb);
#pragma unroll
    for (int q = 0; q < 4; q++) {
        ulonglong2 wv = wr[q];
        fma2(a[2 * q], f, wv.x); fma2(a[2 * q + 1], f, wv.y);
    }
}
__device__ __forceinline__ void axpy16x3(u64* a, const float* wb, const u64* f)
{
    const ulonglong2* wr = reinterpret_cast<const ulonglong2*>(wb);
#pragma unroll
    for (int q = 0; q < 4; q++) {
        ulonglong2 wv = wr[q];
#pragma unroll
        for (int m = 0; m < 3; m++) {
            fma2(a[8 * m + 2 * q], f[m], wv.x); fma2(a[8 * m + 2 * q + 1], f[m], wv.y);
        }
    }
}
__device__ __forceinline__ void axpy16x5(u64* a, const float* wb, const u64* f)
{
    const ulonglong2* wr = reinterpret_cast<const ulonglong2*>(wb);
#pragma unroll
    for (int q = 0; q < 4; q++) {
        ulonglong2 wv = wr[q];
#pragma unroll
        for (int m = 0; m < 5; m++) {
            fma2(a[8 * m + 2 * q], f[m], wv.x); fma2(a[8 * m + 2 * q + 1], f[m], wv.y);
        }
    }
}

// ---- strided component store: acc[8] -> o[base + stride*w + moff], scaled --
__device__ __forceinline__ void store_comp(const u64* acc, float* o, int base,
                                           int stride, int moff, float sc)
{
#pragma unroll
    for (int j = 0; j < 8; j++) {
        float lo, hi; unpk(acc[j], lo, hi);
        o[base + stride * (2 * j)     + moff] = lo * sc;
        o[base + stride * (2 * j + 1) + moff] = hi * sc;
    }
}

// ---- shared x staging: 128 rows transposed to [feature][row] -------------
__device__ __forceinline__ void stage_x(float* xs, const float* __restrict__ x,
                                        int row0, int n, int tid)
{
    const float4* x4 = reinterpret_cast<const float4*>(x);
#pragma unroll
    for (int i = 0; i < 16; i++) {
        int lin = i * TBLK + tid;          // 2048 = 128 rows * 16 float4
        int rr = lin >> 4, c = lin & 15;
        float4 val = make_float4(0.f, 0.f, 0.f, 0.f);
        if (row0 + rr < n) val = x4[(size_t)(row0 + rr) * 16 + c];
        xs[(4 * c + 0) * XSTR + rr] = val.x;
        xs[(4 * c + 1) * XSTR + rr] = val.y;
        xs[(4 * c + 2) * XSTR + rr] = val.z;
        xs[(4 * c + 3) * XSTR + rr] = val.w;
    }
}

// ===========================================================================
// Kernel A: o_2e (path 4), symmetric pairs. 1 row/thread, 40 packed accs.
// ===========================================================================
__global__ __launch_bounds__(TBLK)
void k2e(const float* __restrict__ x, float* __restrict__ out, int n)
{
    extern __shared__ float smem[];
    float* ws = smem;                 // 8704 floats of s4
    float* xs = smem + 8704;
    int tid = threadIdx.x;
    {
        const float4* gw = reinterpret_cast<const float4*>(g_ws + OFF_S4);
        float4* sw = reinterpret_cast<float4*>(ws);
        for (int i = tid; i < 2176; i += TBLK) sw[i] = gw[i];
    }
    int row0 = blockIdx.x * TBLK;
    stage_x(xs, x, row0, n, tid);
    __syncthreads();

    int z = row0 + tid;
    if (z >= n) return;
    float* o = out + (size_t)z * 192;
    const float* xr = xs + tid;

    u64 a[40];
#pragma unroll
    for (int k = 0; k < 40; k++) a[k] = 0ULL;
    const float* s4r = ws;

    for (int u = 0; u < 16; u++) {
        const float* fu = xr + (16 + 3 * u) * XSTR;
        float ax = fu[0], ay = fu[XSTR], az = fu[2 * XSTR];
        {   // diagonal (m-scales applied at epilogue)
            u64 q[5];
            float t0 = ax * ay, t1 = ay * az, t3 = ax * az;
            float pxx = ax * ax, pyy = ay * ay, pzz = az * az;
            q[0] = dup2(t0 + t0);
            q[1] = dup2(t1 + t1);
            float s = pxx + pyy; q[2] = dup2(fmaf(2.f, pzz, -s));
            q[3] = dup2(t3 + t3);
            q[4] = dup2(pxx - pyy);
            axpy16x5(a, s4r, q); s4r += 16;
        }
        for (int v = u + 1; v < 16; v++) {
            const float* fv = xr + (16 + 3 * v) * XSTR;
            float bx = fv[0], by = fv[XSTR], bz = fv[2 * XSTR];
            u64 q[5];
            float pxx = ax * bx, pyy = ay * by, pzz = az * bz;
            q[0] = dup2(fmaf(ax, by, ay * bx));
            q[1] = dup2(fmaf(ay, bz, az * by));
            float s = pxx + pyy; q[2] = dup2(fmaf(2.f, pzz, -s));
            q[3] = dup2(fmaf(ax, bz, az * bx));
            q[4] = dup2(pxx - pyy);
            axpy16x5(a, s4r, q); s4r += 16;
        }
    }
    store_comp(a,      o, 112, 5, 0, S2F);
    store_comp(a + 8,  o, 112, 5, 1, S2F);
    store_comp(a + 16, o, 112, 5, 2, IS6F);
    store_comp(a + 24, o, 112, 5, 3, S2F);
    store_comp(a + 32, o, 112, 5, 4, S2F);
}

// ===========================================================================
// Kernel B: o_0e (paths 0+2) + o_1e (path 3). 1 row/thread, 32 packed accs.
// ===========================================================================
__global__ __launch_bounds__(TBLK)
void k0e1e(const float* __restrict__ x, float* __restrict__ out, int n)
{
    extern __shared__ float smem[];
    float* ws = smem;                 // s0 [0,2176) s2 [2176,4352) a3 [4352,6272)
    float* xs = smem + 6272;
    int tid = threadIdx.x;
    {
        const float4* g1 = reinterpret_cast<const float4*>(g_ws + OFF_S0);
        float4* sw = reinterpret_cast<float4*>(ws);
        for (int i = tid; i < 1088; i += TBLK) sw[i] = g1[i];       // s0+s2
        const float4* g2 = reinterpret_cast<const float4*>(g_ws + OFF_A3);
        for (int i = tid; i < 480; i += TBLK) sw[1088 + i] = g2[i]; // a3
    }
    int row0 = blockIdx.x * TBLK;
    stage_x(xs, x, row0, n, tid);
    __syncthreads();

    int z = row0 + tid;
    if (z >= n) return;
    float* o = out + (size_t)z * 192;
    const float* xr = xs + tid;

    u64 c0[8], e1[24];
#pragma unroll
    for (int k = 0; k < 8; k++)  c0[k] = 0ULL;
#pragma unroll
    for (int k = 0; k < 24; k++) e1[k] = 0ULL;
    const float* s0r = ws;
    const float* s2r = ws + 2176;
    const float* a3r = ws + 4352;

    for (int u = 0; u < 16; u++) {
        float a0 = xr[u * XSTR];
        const float* fu = xr + (16 + 3 * u) * XSTR;
        float ax = fu[0], ay = fu[XSTR], az = fu[2 * XSTR];
        {   // diagonal: cross vanishes
            float s = a0 * a0;
            float d = fmaf(ax, ax, fmaf(ay, ay, az * az));
            axpy16(c0, s0r, dup2(s)); s0r += 16;
            axpy16(c0, s2r, dup2(d)); s2r += 16;
        }
        for (int v = u + 1; v < 16; v++) {
            float b0 = xr[v * XSTR];
            const float* fv = xr + (16 + 3 * v) * XSTR;
            float bx = fv[0], by = fv[XSTR], bz = fv[2 * XSTR];
            float s = a0 * b0;
            float d = fmaf(ax, bx, fmaf(ay, by, az * bz));
            u64 c[3];
            c[0] = dup2(fmaf(ay, bz, -(az * by)));
            c[1] = dup2(fmaf(az, bx, -(ax * bz)));
            c[2] = dup2(fmaf(ax, by, -(ay * bx)));
            axpy16(c0, s0r, dup2(s)); s0r += 16;
            axpy16(c0, s2r, dup2(d)); s2r += 16;
            axpy16x3(e1, a3r, c);     a3r += 16;
        }
    }
    {   // o_0e: contiguous, vectorized
        float ob[16];
#pragma unroll
        for (int j = 0; j < 8; j++) unpk(c0[j], ob[2 * j], ob[2 * j + 1]);
        float4* o4 = reinterpret_cast<float4*>(o);
#pragma unroll
        for (int j = 0; j < 4; j++)
            o4[j] = make_float4(ob[4 * j], ob[4 * j + 1], ob[4 * j + 2], ob[4 * j + 3]);
    }
    store_comp(e1,      o, 64, 3, 0, 1.0f);
    store_comp(e1 + 8,  o, 64, 3, 1, 1.0f);
    store_comp(e1 + 16, o, 64, 3, 2, 1.0f);
}

// ===========================================================================
// Kernel C: o_1o (path 1, 0e x 1o -> 1o), factorized. 1 row/thread, 24 accs.
//   T_v[w] = sum_u a0_u * W1[u,v,w];  o[w,m] += T_v[w] * b_v[m]
// ===========================================================================
__global__ __launch_bounds__(TBLK)
void k1o(const float* __restrict__ x, float* __restrict__ out, int n)
{
    extern __shared__ float smem[];
    float* ws = smem;                 // 4096 floats of w1
    float* xs = smem + 4096;
    int tid = threadIdx.x;
    {
        const float4* gw = reinterpret_cast<const float4*>(g_ws + OFF_W1);
        float4* sw = reinterpret_cast<float4*>(ws);
        for (int i = tid; i < 1024; i += TBLK) sw[i] = gw[i];
    }
    int row0 = blockIdx.x * TBLK;
    stage_x(xs, x, row0, n, tid);
    __syncthreads();

    int z = row0 + tid;
    if (z >= n) return;
    float* o = out + (size_t)z * 192;
    const float* xr = xs + tid;

    float a0[16];
#pragma unroll
    for (int u = 0; u < 16; u++) a0[u] = xr[u * XSTR];

    u64 p[24];
#pragma unroll
    for (int k = 0; k < 24; k++) p[k] = 0ULL;

    for (int v = 0; v < 16; v++) {
        u64 T[8];
        {
            u64 d = dup2(a0[0]);
            const ulonglong2* wr = reinterpret_cast<const ulonglong2*>(ws + v * 16);
#pragma unroll
            for (int t = 0; t < 4; t++) {
                ulonglong2 wv = wr[t];
                T[2 * t] = mul2(d, wv.x); T[2 * t + 1] = mul2(d, wv.y);
            }
        }
#pragma unroll
        for (int u = 1; u < 16; u++) {
            u64 d = dup2(a0[u]);
            const ulonglong2* wr = reinterpret_cast<const ulonglong2*>(ws + u * 256 + v * 16);
#pragma unroll
            for (int t = 0; t < 4; t++) {
                ulonglong2 wv = wr[t];
                fma2(T[2 * t], d, wv.x); fma2(T[2 * t + 1], d, wv.y);
            }
        }
        const float* fv = xr + (16 + 3 * v) * XSTR;
        u64 xd = dup2(fv[0]), yd = dup2(fv[XSTR]), zd = dup2(fv[2 * XSTR]);
#pragma unroll
        for (int h = 0; h < 8; h++) {
            fma2(p[h], T[h], xd);
            fma2(p[8 + h], T[h], yd);
            fma2(p[16 + h], T[h], zd);
        }
    }
    store_comp(p,      o, 16, 3, 0, 1.0f);
    store_comp(p + 8,  o, 16, 3, 1, 1.0f);
    store_comp(p + 16, o, 16, 3, 2, 1.0f);
}

// ---------------------------------------------------------------------------
extern "C" void kernel_launch(void* const* d_in, const int* in_sizes, int n_in,
                              void* d_out, int out_size)
{
    const float* x  = (const float*)d_in[0];
    const float* w0 = (const float*)d_in[1];
    const float* w1 = (const float*)d_in[2];
    const float* w2 = (const float*)d_in[3];
    const float* w3 = (const float*)d_in[4];
    const float* w4 = (const float*)d_in[5];
    float* out = (float*)d_out;
    int n = in_sizes[0] / 64;
    int grid = (n + TBLK - 1) / TBLK;

    cudaFuncSetAttribute(k2e,   cudaFuncAttributeMaxDynamicSharedMemorySize, SMEM_A_BYTES);
    cudaFuncSetAttribute(k0e1e, cudaFuncAttributeMaxDynamicSharedMemorySize, SMEM_B_BYTES);
    cudaFuncSetAttribute(k1o,   cudaFuncAttributeMaxDynamicSharedMemorySize, SMEM_C_BYTES);

    prep_kernel<<<16, 256>>>(w0, w1, w2, w3, w4);
    k2e  <<<grid, TBLK, SMEM_A_BYTES>>>(x, out, n);
    k0e1e<<<grid, TBLK, SMEM_B_BYTES>>>(x, out, n);
    k1o  <<<grid, TBLK, SMEM_C_BYTES>>>(x, out, n);
}

// round 16
// speedup vs baseline: 1.6522x; 1.6522x over previous
#include <cuda_runtime.h>

typedef unsigned long long u64;

#define BLK   256
#define TROWS 256   // rows per block (2 per thread)
#define XSTR  258   // padded float stride for transposed x tile

#define OFF_S0 0        // 136*16 symmetric w0  (scaled a2)
#define OFF_S2 2176     // 136*16 symmetric w2  (scaled a2/sqrt3)
#define OFF_S4 4352     // 136*16 symmetric w4  (scaled a1; m-scales in epilogue)
#define OFF_A3 6528     // 120*16 antisym  w3   (scaled a1/sqrt2)
#define OFF_W1 8448     // 256*16 w1            (scaled a1)
#define W_TOTAL 12544
#define SMEM_FLOATS (W_TOTAL + 64 * XSTR)
#define SMEM_BYTES  (SMEM_FLOATS * 4)

#define A1F    0.0625f
#define A2F    0.04419417382415922f
#define A2_3F  0.02551551815399144f
#define A1S2F  0.04419417382415922f
#define S2F    0.7071067811865476f
#define IS6F   0.4082482904638630f

__device__ float g_ws[W_TOTAL];

__global__ void prep_kernel(const float* __restrict__ w0, const float* __restrict__ w1,
                            const float* __restrict__ w2, const float* __restrict__ w3,
                            const float* __restrict__ w4)
{
    int idx = blockIdx.x * blockDim.x + threadIdx.x;
    if (idx >= 4096) return;
    int w = idx & 15;
    int v = (idx >> 4) & 15;
    int u = idx >> 8;
    int sidx = ((v * 16 + u) << 4) + w;

    g_ws[OFF_W1 + idx] = A1F * w1[idx];

    if (u <= v) {
        int p = u * 16 - (u * (u - 1)) / 2 + (v - u);
        float f0 = (u == v) ? w0[idx] : (w0[idx] + w0[sidx]);
        float f2 = (u == v) ? w2[idx] : (w2[idx] + w2[sidx]);
        float f4 = (u == v) ? w4[idx] : (w4[idx] + w4[sidx]);
        g_ws[OFF_S0 + p * 16 + w] = A2F   * f0;
        g_ws[OFF_S2 + p * 16 + w] = A2_3F * f2;
        g_ws[OFF_S4 + p * 16 + w] = A1F   * f4;
    }
    if (u < v) {
        int pa = 15 * u - (u * (u - 1)) / 2 + (v - u - 1);
        g_ws[OFF_A3 + pa * 16 + w] = A1S2F * (w3[idx] - w3[sidx]);
    }
}

// ---- packed fp32 helpers -------------------------------------------------
__device__ __forceinline__ u64 dup2(float s)
{
    unsigned int b = __float_as_uint(s);
    u64 r;
    asm("mov.b64 %0, {%1, %1};" : "=l"(r) : "r"(b));
    return r;
}
__device__ __forceinline__ void fma2(u64& d, u64 a, u64 b)
{
    asm("fma.rn.f32x2 %0, %1, %2, %0;" : "+l"(d) : "l"(a), "l"(b));
}
__device__ __forceinline__ u64 mul2(u64 a, u64 b)
{
    u64 d;
    asm("mul.rn.f32x2 %0, %1, %2;" : "=l"(d) : "l"(a), "l"(b));
    return d;
}
__device__ __forceinline__ void unpk(u64 v, float& lo, float& hi)
{
    unsigned int l, h;
    asm("mov.b64 {%0, %1}, %2;" : "=r"(l), "=r"(h) : "l"(v));
    lo = __uint_as_float(l);
    hi = __uint_as_float(h);
}

// ---- dual-row axpy: one weight-row load feeds both rows' accumulators ----
__device__ __forceinline__ void axpy16_2(u64* aA, u64* aB, const float* wb, u64 fA, u64 fB)
{
    const ulonglong2* wr = reinterpret_cast<const ulonglong2*>(wb);
#pragma unroll
    for (int q = 0; q < 4; q++) {
        ulonglong2 wv = wr[q];
        fma2(aA[2 * q], fA, wv.x); fma2(aA[2 * q + 1], fA, wv.y);
        fma2(aB[2 * q], fB, wv.x); fma2(aB[2 * q + 1], fB, wv.y);
    }
}
__device__ __forceinline__ void axpy16x3_2(u64* aA, u64* aB, const float* wb,
                                           const u64* fA, const u64* fB)
{
    const ulonglong2* wr = reinterpret_cast<const ulonglong2*>(wb);
#pragma unroll
    for (int q = 0; q < 4; q++) {
        ulonglong2 wv = wr[q];
#pragma unroll
        for (int m = 0; m < 3; m++) {
            fma2(aA[8 * m + 2 * q], fA[m], wv.x); fma2(aA[8 * m + 2 * q + 1], fA[m], wv.y);
            fma2(aB[8 * m + 2 * q], fB[m], wv.x); fma2(aB[8 * m + 2 * q + 1], fB[m], wv.y);
        }
    }
}
__device__ __forceinline__ void axpy16x5_2(u64* aA, u64* aB, const float* wb,
                                           const u64* fA, const u64* fB)
{
    const ulonglong2* wr = reinterpret_cast<const ulonglong2*>(wb);
#pragma unroll
    for (int q = 0; q < 4; q++) {
        ulonglong2 wv = wr[q];
#pragma unroll
        for (int m = 0; m < 5; m++) {
            fma2(aA[8 * m + 2 * q], fA[m], wv.x); fma2(aA[8 * m + 2 * q + 1], fA[m], wv.y);
            fma2(aB[8 * m + 2 * q], fB[m], wv.x); fma2(aB[8 * m + 2 * q + 1], fB[m], wv.y);
        }
    }
}

// ---- output writers ------------------------------------------------------
__device__ __forceinline__ void store_0e(const u64* acc, float* o)
{
    float ob[16];
#pragma unroll
    for (int j = 0; j < 8; j++) unpk(acc[j], ob[2 * j], ob[2 * j + 1]);
    float4* o4 = reinterpret_cast<float4*>(o);
#pragma unroll
    for (int j = 0; j < 4; j++)
        o4[j] = make_float4(ob[4 * j], ob[4 * j + 1], ob[4 * j + 2], ob[4 * j + 3]);
}
__device__ __forceinline__ void store_1e(const u64* acc, float* o)
{
    float ob[48];
#pragma unroll
    for (int m = 0; m < 3; m++)
#pragma unroll
        for (int j = 0; j < 8; j++) {
            float lo, hi; unpk(acc[m * 8 + j], lo, hi);
            ob[(2 * j) * 3 + m] = lo; ob[(2 * j + 1) * 3 + m] = hi;
        }
    float4* o4 = reinterpret_cast<float4*>(o + 64);
#pragma unroll
    for (int j = 0; j < 12; j++)
        o4[j] = make_float4(ob[4 * j], ob[4 * j + 1], ob[4 * j + 2], ob[4 * j + 3]);
}
__device__ __forceinline__ void store_2e(const u64* acc, float* o)
{
    const float csc[5] = {S2F, S2F, IS6F, S2F, S2F};   // epilogue m-scales
    float ob[80];
#pragma unroll
    for (int m = 0; m < 5; m++)
#pragma unroll
        for (int j = 0; j < 8; j++) {
            float lo, hi; unpk(acc[m * 8 + j], lo, hi);
            ob[(2 * j) * 5 + m] = lo * csc[m]; ob[(2 * j + 1) * 5 + m] = hi * csc[m];
        }
    float4* o4 = reinterpret_cast<float4*>(o + 112);
#pragma unroll
    for (int j = 0; j < 20; j++)
        o4[j] = make_float4(ob[4 * j], ob[4 * j + 1], ob[4 * j + 2], ob[4 * j + 3]);
}
__device__ __forceinline__ void store_1o_half(const u64* acc, float* o, int role)
{
    float ob[24];
#pragma unroll
    for (int m = 0; m < 3; m++)
#pragma unroll
        for (int j = 0; j < 4; j++) {
            float lo, hi; unpk(acc[m * 4 + j], lo, hi);
            ob[(2 * j) * 3 + m] = lo; ob[(2 * j + 1) * 3 + m] = hi;
        }
    float4* o4 = reinterpret_cast<float4*>(o + 16 + role * 24);
#pragma unroll
    for (int j = 0; j < 6; j++)
        o4[j] = make_float4(ob[4 * j], ob[4 * j + 1], ob[4 * j + 2], ob[4 * j + 3]);
}

// ---------------------------------------------------------------------------
// R10 structure + software-pipelined feature loads:
//   2 threads per row (role split), dual-row weight amortization.
//   role 0 (warps 0-3): o_2e sym pass + o_1o[w 0..7]
//   role 1 (warps 4-7): o_0e + o_1e sym pass + o_1o[w 8..15]
// Each v-iteration prefetches v+1's features so LDS latency hides under the
// current pair's FFMA2 stream (ptxas won't pipeline across iterations itself).
// ---------------------------------------------------------------------------
__global__ __launch_bounds__(BLK, 1)
void tsq_kernel(const float* __restrict__ x, float* __restrict__ out, int n)
{
    extern __shared__ float smem[];
    float* ws = smem;
    float* xs = smem + W_TOTAL;
    int tid = threadIdx.x;

    {
        const float4* gw = reinterpret_cast<const float4*>(g_ws);
        float4* sw = reinterpret_cast<float4*>(ws);
        for (int i = tid; i < W_TOTAL / 4; i += BLK) sw[i] = gw[i];
    }
    int row0 = blockIdx.x * TROWS;
    {
        const float4* x4 = reinterpret_cast<const float4*>(x);
#pragma unroll
        for (int i = 0; i < 16; i++) {
            int lin = i * BLK + tid;            // 4096 = 256 rows * 16 float4
            int rr = lin >> 4, c = lin & 15;
            float4 val = make_float4(0.f, 0.f, 0.f, 0.f);
            if (row0 + rr < n) val = x4[(size_t)(row0 + rr) * 16 + c];
            xs[(4 * c + 0) * XSTR + rr] = val.x;
            xs[(4 * c + 1) * XSTR + rr] = val.y;
            xs[(4 * c + 2) * XSTR + rr] = val.z;
            xs[(4 * c + 3) * XSTR + rr] = val.w;
        }
    }
    __syncthreads();

    int role = tid >> 7;
    int r    = tid & 127;
    int zA = row0 + r;
    if (zA >= n) return;
    int zB = zA + 128;
    bool vB = (zB < n);
    float* oA = out + (size_t)zA * 192;
    float* oB = out + (size_t)zB * 192;
    const float* xr = xs + r;

    if (role == 0) {
        // ===== o_2e, symmetric pairs, feature loads rotated one iter ahead
        u64 aA[40], aB[40];
#pragma unroll
        for (int k = 0; k < 40; k++) { aA[k] = 0ULL; aB[k] = 0ULL; }
        const float* s4r = ws + OFF_S4;

        for (int u = 0; u < 16; u++) {
            const float* fu = xr + (16 + 3 * u) * XSTR;
            float axA = fu[0],   ayA = fu[XSTR],       azA = fu[2 * XSTR];
            float axB = fu[128], ayB = fu[XSTR + 128], azB = fu[2 * XSTR + 128];
            // prefetch first v's features (hidden under diagonal axpy)
            float bxA = 0.f, byA = 0.f, bzA = 0.f, bxB = 0.f, byB = 0.f, bzB = 0.f;
            if (u < 15) {
                const float* fp = xr + (16 + 3 * (u + 1)) * XSTR;
                bxA = fp[0];   byA = fp[XSTR];       bzA = fp[2 * XSTR];
                bxB = fp[128]; byB = fp[XSTR + 128]; bzB = fp[2 * XSTR + 128];
            }
            {   // diagonal (features = 2*prod; m-scales applied at epilogue)
                u64 dA[5], dB[5];
                {
                    float pxx = axA * axA, pyy = ayA * ayA, pzz = azA * azA;
                    float t;
                    t = axA * ayA; dA[0] = dup2(t + t);
                    t = ayA * azA; dA[1] = dup2(t + t);
                    float s = pxx + pyy; dA[2] = dup2(fmaf(2.f, pzz, -s));
                    t = axA * azA; dA[3] = dup2(t + t);
                    dA[4] = dup2(pxx - pyy);
                }
                {
                    float pxx = axB * axB, pyy = ayB * ayB, pzz = azB * azB;
                    float t;
                    t = axB * ayB; dB[0] = dup2(t + t);
                    t = ayB * azB; dB[1] = dup2(t + t);
                    float s = pxx + pyy; dB[2] = dup2(fmaf(2.f, pzz, -s));
                    t = axB * azB; dB[3] = dup2(t + t);
                    dB[4] = dup2(pxx - pyy);
                }
                axpy16x5_2(aA, aB, s4r, dA, dB); s4r += 16;
            }
            for (int v = u + 1; v < 16; v++) {
                // prefetch next iteration's features (retires under this axpy)
                int vn = (v < 15) ? v + 1 : 15;
                const float* fn = xr + (16 + 3 * vn) * XSTR;
                float nxA = fn[0],   nyA = fn[XSTR],       nzA = fn[2 * XSTR];
                float nxB = fn[128], nyB = fn[XSTR + 128], nzB = fn[2 * XSTR + 128];

                u64 dA[5], dB[5];
                {
                    float pxx = axA * bxA, pyy = ayA * byA, pzz = azA * bzA;
                    dA[0] = dup2(fmaf(axA, byA, ayA * bxA));
                    dA[1] = dup2(fmaf(ayA, bzA, azA * byA));
                    float s = pxx + pyy; dA[2] = dup2(fmaf(2.f, pzz, -s));
                    dA[3] = dup2(fmaf(axA, bzA, azA * bxA));
                    dA[4] = dup2(pxx - pyy);
                }
                {
                    float pxx = axB * bxB, pyy = ayB * byB, pzz = azB * bzB;
                    dB[0] = dup2(fmaf(axB, byB, ayB * bxB));
                    dB[1] = dup2(fmaf(ayB, bzB, azB * byB));
                    float s = pxx + pyy; dB[2] = dup2(fmaf(2.f, pzz, -s));
                    dB[3] = dup2(fmaf(axB, bzB, azB * bxB));
                    dB[4] = dup2(pxx - pyy);
                }
                axpy16x5_2(aA, aB, s4r, dA, dB); s4r += 16;
                bxA = nxA; byA = nyA; bzA = nzA;
                bxB = nxB; byB = nyB; bzB = nzB;
            }
        }
        store_2e(aA, oA);
        if (vB) store_2e(aB, oB);
    } else {
        // ===== o_0e (paths 0+2) and o_1e (path 3), rotated feature loads
        u64 c0A[8], c0B[8], e1A[24], e1B[24];
#pragma unroll
        for (int k = 0; k < 8; k++)  { c0A[k] = 0ULL; c0B[k] = 0ULL; }
#pragma unroll
        for (int k = 0; k < 24; k++) { e1A[k] = 0ULL; e1B[k] = 0ULL; }
        const float* s0r = ws + OFF_S0;
        const float* s2r = ws + OFF_S2;
        const float* a3r = ws + OFF_A3;

        for (int u = 0; u < 16; u++) {
            float a0A = xr[u * XSTR], a0B = xr[u * XSTR + 128];
            const float* fu = xr + (16 + 3 * u) * XSTR;
            float axA = fu[0],   ayA = fu[XSTR],       azA = fu[2 * XSTR];
            float axB = fu[128], ayB = fu[XSTR + 128], azB = fu[2 * XSTR + 128];
            float b0A = 0.f, b0B = 0.f;
            float bxA = 0.f, byA = 0.f, bzA = 0.f, bxB = 0.f, byB = 0.f, bzB = 0.f;
            if (u < 15) {
                b0A = xr[(u + 1) * XSTR]; b0B = xr[(u + 1) * XSTR + 128];
                const float* fp = xr + (16 + 3 * (u + 1)) * XSTR;
                bxA = fp[0];   byA = fp[XSTR];       bzA = fp[2 * XSTR];
                bxB = fp[128]; byB = fp[XSTR + 128]; bzB = fp[2 * XSTR + 128];
            }
            {   // diagonal
                float sA = a0A * a0A, sB = a0B * a0B;
                float dA = fmaf(axA, axA, fmaf(ayA, ayA, azA * azA));
                float dB = fmaf(axB, axB, fmaf(ayB, ayB, azB * azB));
                axpy16_2(c0A, c0B, s0r, dup2(sA), dup2(sB)); s0r += 16;
                axpy16_2(c0A, c0B, s2r, dup2(dA), dup2(dB)); s2r += 16;
            }
            for (int v = u + 1; v < 16; v++) {
                int vn = (v < 15) ? v + 1 : 15;
                float n0A = xr[vn * XSTR], n0B = xr[vn * XSTR + 128];
                const float* fn = xr + (16 + 3 * vn) * XSTR;
                float nxA = fn[0],   nyA = fn[XSTR],       nzA = fn[2 * XSTR];
                float nxB = fn[128], nyB = fn[XSTR + 128], nzB = fn[2 * XSTR + 128];

                float sA = a0A * b0A, sB = a0B * b0B;
                float dA = fmaf(axA, bxA, fmaf(ayA, byA, azA * bzA));
                float dB = fmaf(axB, bxB, fmaf(ayB, byB, azB * bzB));
                u64 cA[3], cB[3];
                cA[0] = dup2(fmaf(ayA, bzA, -(azA * byA)));
                cA[1] = dup2(fmaf(azA, bxA, -(axA * bzA)));
                cA[2] = dup2(fmaf(axA, byA, -(ayA * bxA)));
                cB[0] = dup2(fmaf(ayB, bzB, -(azB * byB)));
                cB[1] = dup2(fmaf(azB, bxB, -(axB * bzB)));
                cB[2] = dup2(fmaf(axB, byB, -(ayB * bxB)));

                axpy16_2(c0A, c0B, s0r, dup2(sA), dup2(sB)); s0r += 16;
                axpy16_2(c0A, c0B, s2r, dup2(dA), dup2(dB)); s2r += 16;
                axpy16x3_2(e1A, e1B, a3r, cA, cB);           a3r += 16;

                b0A = n0A; b0B = n0B;
                bxA = nxA; byA = nyA; bzA = nzA;
                bxB = nxB; byB = nyB; bzB = nzB;
            }
        }
        store_0e(c0A, oA);
        store_1e(e1A, oA);
        if (vB) { store_0e(c0B, oB); store_1e(e1B, oB); }
    }

    // ===== path 1 (0e x 1o -> 1o), factorized; role handles 8 of 16 w.
    // a0 kept as floats (halved live regs vs pre-dup'd); dup in-loop on ALU pipe.
    {
        float a0A[16], a0B[16];
#pragma unroll
        for (int u = 0; u < 16; u++) {
            a0A[u] = xr[u * XSTR];
            a0B[u] = xr[u * XSTR + 128];
        }
        u64 pA[12], pB[12];
#pragma unroll
        for (int k = 0; k < 12; k++) { pA[k] = 0ULL; pB[k] = 0ULL; }

        const float* w1b = ws + OFF_W1 + role * 8;

        for (int v = 0; v < 16; v++) {
            // feature loads first: retire under the 16-u T accumulation
            const float* fv = xr + (16 + 3 * v) * XSTR;
            float fxA = fv[0],   fyA = fv[XSTR],       fzA = fv[2 * XSTR];
            float fxB = fv[128], fyB = fv[XSTR + 128], fzB = fv[2 * XSTR + 128];

            u64 TA[4], TB[4];
            {
                u64 dA = dup2(a0A[0]), dB = dup2(a0B[0]);
                const ulonglong2* wr = reinterpret_cast<const ulonglong2*>(w1b + v * 16);
                ulonglong2 w01 = wr[0], w23 = wr[1];
                TA[0] = mul2(dA, w01.x); TA[1] = mul2(dA, w01.y);
                TA[2] = mul2(dA, w23.x); TA[3] = mul2(dA, w23.y);
                TB[0] = mul2(dB, w01.x); TB[1] = mul2(dB, w01.y);
                TB[2] = mul2(dB, w23.x); TB[3] = mul2(dB, w23.y);
            }
#pragma unroll
            for (int u = 1; u < 16; u++) {
                u64 dA = dup2(a0A[u]), dB = dup2(a0B[u]);
                const ulonglong2* wr =
                    reinterpret_cast<const ulonglong2*>(w1b + u * 256 + v * 16);
                ulonglong2 w01 = wr[0], w23 = wr[1];
                fma2(TA[0], dA, w01.x); fma2(TA[1], dA, w01.y);
                fma2(TA[2], dA, w23.x); fma2(TA[3], dA, w23.y);
                fma2(TB[0], dB, w01.x); fma2(TB[1], dB, w01.y);
                fma2(TB[2], dB, w23.x); fma2(TB[3], dB, w23.y);
            }
            u64 xdA = dup2(fxA), ydA = dup2(fyA), zdA = dup2(fzA);
            u64 xdB = dup2(fxB), ydB = dup2(fyB), zdB = dup2(fzB);
#pragma unroll
            for (int j = 0; j < 4; j++) {
                fma2(pA[j], TA[j], xdA); fma2(pA[4 + j], TA[j], ydA); fma2(pA[8 + j], TA[j], zdA);
                fma2(pB[j], TB[j], xdB); fma2(pB[4 + j], TB[j], ydB); fma2(pB[8 + j], TB[j], zdB);
            }
        }
        store_1o_half(pA, oA, role);
        if (vB) store_1o_half(pB, oB, role);
    }
}

// ---------------------------------------------------------------------------
extern "C" void kernel_launch(void* const* d_in, const int* in_sizes, int n_in,
                              void* d_out, int out_size)
{
    const float* x  = (const float*)d_in[0];
    const float* w0 = (const float*)d_in[1];
    const float* w1 = (const float*)d_in[2];
    const float* w2 = (const float*)d_in[3];
    const float* w3 = (const float*)d_in[4];
    const float* w4 = (const float*)d_in[5];
    float* out = (float*)d_out;
    int n = in_sizes[0] / 64;

    cudaFuncSetAttribute(tsq_kernel, cudaFuncAttributeMaxDynamicSharedMemorySize, SMEM_BYTES);

    prep_kernel<<<16, 256>>>(w0, w1, w2, w3, w4);
    tsq_kernel<<<(n + TROWS - 1) / TROWS, BLK, SMEM_BYTES>>>(x, out, n);
}